// round 5
// baseline (speedup 1.0000x reference)
#include <cuda_runtime.h>
#include <cuda_bf16.h>
#include <cuda_fp8.h>
#include <cstdint>

// ===========================================================================
// Problem-fixed maxima (B=4,S=2048,K=4096,N=4096)
#define M_FIX 8192
#define N_FIX 4096
#define K_FIX 4096

__device__ __nv_bfloat16 g_A[(size_t)M_FIX * K_FIX];   // bf16 dequantized activations
__device__ __nv_bfloat16 g_B[(size_t)N_FIX * K_FIX];   // bf16 scaled weights
__device__ unsigned int  g_amax_bits;

// ===========================================================================
__global__ void reset_kernel() { g_amax_bits = 0u; }

__global__ void amax_kernel(const float* __restrict__ x, long long n4) {
    const float4* x4 = reinterpret_cast<const float4*>(x);
    float m = 0.f;
    long long stride = (long long)gridDim.x * blockDim.x;
    for (long long i = blockIdx.x * (long long)blockDim.x + threadIdx.x; i < n4; i += stride) {
        float4 v = x4[i];
        m = fmaxf(m, fabsf(__bfloat162float(__float2bfloat16(v.x))));
        m = fmaxf(m, fabsf(__bfloat162float(__float2bfloat16(v.y))));
        m = fmaxf(m, fabsf(__bfloat162float(__float2bfloat16(v.z))));
        m = fmaxf(m, fabsf(__bfloat162float(__float2bfloat16(v.w))));
    }
#pragma unroll
    for (int o = 16; o > 0; o >>= 1) m = fmaxf(m, __shfl_xor_sync(0xffffffffu, m, o));
    __shared__ float sm[32];
    int lane = threadIdx.x & 31, w = threadIdx.x >> 5;
    if (lane == 0) sm[w] = m;
    __syncthreads();
    if (w == 0) {
        int nw = (blockDim.x + 31) >> 5;
        m = (lane < nw) ? sm[lane] : 0.f;
#pragma unroll
        for (int o = 16; o > 0; o >>= 1) m = fmaxf(m, __shfl_xor_sync(0xffffffffu, m, o));
        if (lane == 0) atomicMax(&g_amax_bits, __float_as_uint(m));
    }
}

__device__ __forceinline__ unsigned short quant1(float v, float scale, __nv_bfloat16 sb) {
    float xf = __bfloat162float(__float2bfloat16(v));    // bf16(x)
    float q  = __fdiv_rn(xf, scale);
    q = fminf(fmaxf(q, -448.0f), 448.0f);
    __nv_fp8_e4m3 f8(q);
    float fq = (float)f8;
    return __bfloat16_as_ushort(__hmul(__float2bfloat16(fq), sb));
}

__global__ void quant_kernel(const float* __restrict__ x, long long n4) {
    float amax  = __uint_as_float(g_amax_bits);
    float scale = fmaxf(amax, 1e-12f) / 448.0f;
    __nv_bfloat16 sb = __float2bfloat16(scale);
    const float4* x4 = reinterpret_cast<const float4*>(x);
    ushort4* a4 = reinterpret_cast<ushort4*>(g_A);
    long long stride = (long long)gridDim.x * blockDim.x;
    for (long long i = blockIdx.x * (long long)blockDim.x + threadIdx.x; i < n4; i += stride) {
        float4 v = x4[i];
        ushort4 o;
        o.x = quant1(v.x, scale, sb);
        o.y = quant1(v.y, scale, sb);
        o.z = quant1(v.z, scale, sb);
        o.w = quant1(v.w, scale, sb);
        a4[i] = o;
    }
}

__global__ void prep_w_kernel(const float* __restrict__ w,
                              const float* __restrict__ wscale, long long n4) {
    __nv_bfloat16 sb = __float2bfloat16(wscale[0]);
    const float4* w4 = reinterpret_cast<const float4*>(w);
    ushort4* b4 = reinterpret_cast<ushort4*>(g_B);
    long long stride = (long long)gridDim.x * blockDim.x;
    for (long long i = blockIdx.x * (long long)blockDim.x + threadIdx.x; i < n4; i += stride) {
        float4 v = w4[i];
        ushort4 o;
        o.x = __bfloat16_as_ushort(__hmul(__float2bfloat16(v.x), sb));
        o.y = __bfloat16_as_ushort(__hmul(__float2bfloat16(v.y), sb));
        o.z = __bfloat16_as_ushort(__hmul(__float2bfloat16(v.z), sb));
        o.w = __bfloat16_as_ushort(__hmul(__float2bfloat16(v.w), sb));
        b4[i] = o;
    }
}

// ===========================================================================
// HMMA GEMM: 128x256 CTA tile, BK=64, 8 warps (2M x 4N), warp tile 64x64.
// 3-stage cp.async pipeline, SW128 swizzle, ldmatrix + mma.sync m16n8k16.
// out_f32 = float( bf16(acc) + bf16(bias) )

#define BM 128
#define BN 256
#define BK 64
#define A_BYTES (BM * 128)           // 16 KB
#define B_BYTES (BN * 128)           // 32 KB
#define STAGE_BYTES (A_BYTES + B_BYTES)  // 48 KB
#define NSTAGE 3
#define SW128(off) ((off) ^ (((off) >> 3) & 0x70))

#define CP_ASYNC_16(dst, src) \
    asm volatile("cp.async.cg.shared.global [%0], [%1], 16;" :: "r"(dst), "l"(src))
#define CP_COMMIT() asm volatile("cp.async.commit_group;" ::: "memory")

#define LDMATRIX_X4(r0, r1, r2, r3, addr) \
    asm volatile("ldmatrix.sync.aligned.m8n8.x4.shared.b16 {%0,%1,%2,%3}, [%4];" \
        : "=r"(r0), "=r"(r1), "=r"(r2), "=r"(r3) : "r"(addr))

#define MMA_16816(c0,c1,c2,c3, a0,a1,a2,a3, b0,b1) \
    asm volatile("mma.sync.aligned.m16n8k16.row.col.f32.bf16.bf16.f32 " \
        "{%0,%1,%2,%3}, {%4,%5,%6,%7}, {%8,%9}, {%0,%1,%2,%3};" \
        : "+f"(c0), "+f"(c1), "+f"(c2), "+f"(c3) \
        : "r"(a0), "r"(a1), "r"(a2), "r"(a3), "r"(b0), "r"(b1))

__device__ __forceinline__ uint32_t smem_u32(const void* p) {
    uint32_t a;
    asm("{ .reg .u64 t; cvta.to.shared.u64 t, %1; cvt.u32.u64 %0, t; }" : "=r"(a) : "l"(p));
    return a;
}

__device__ __forceinline__ void fill_stage(uint32_t sbase, int stage,
                                           const __nv_bfloat16* gA, const __nv_bfloat16* gB,
                                           int k0, int ld_row, int ld_unit, int K) {
    const uint32_t st = (uint32_t)stage * STAGE_BYTES;
    // A: 128 rows (4 iters of 32)
#pragma unroll
    for (int it = 0; it < 4; it++) {
        uint32_t off = (uint32_t)(ld_row + it * 32) * 128u + (uint32_t)ld_unit * 16u;
        CP_ASYNC_16(sbase + st + SW128(off), gA + (size_t)(it * 32) * K + k0);
    }
    // B: 256 rows (8 iters of 32)
#pragma unroll
    for (int it = 0; it < 8; it++) {
        uint32_t off = (uint32_t)(ld_row + it * 32) * 128u + (uint32_t)ld_unit * 16u;
        CP_ASYNC_16(sbase + st + A_BYTES + SW128(off), gB + (size_t)(it * 32) * K + k0);
    }
    CP_COMMIT();
}

__global__ __launch_bounds__(256) void gemm_hmma_kernel(const float* __restrict__ bias,
                                                        float* __restrict__ out,
                                                        int M, int N, int K) {
    extern __shared__ char smem[];
    const uint32_t sbase = smem_u32(smem);

    const int tid  = threadIdx.x;
    const int wid  = tid >> 5;
    const int lane = tid & 31;
    const int wm = wid & 1;          // 0..1 -> 64-row slice
    const int wn = wid >> 1;         // 0..3 -> 64-col slice
    const int bm = blockIdx.y * BM;
    const int bn = blockIdx.x * BN;

    const int ld_row  = tid >> 3;    // 0..31
    const int ld_unit = tid & 7;     // 16B unit within 128B row
    const __nv_bfloat16* gA = g_A + (size_t)(bm + ld_row) * K + ld_unit * 8;
    const __nv_bfloat16* gB = g_B + (size_t)(bn + ld_row) * K + ld_unit * 8;

    // ldmatrix addressing
    const int a_r  = wm * 64 + (lane & 15);
    const int a_cu = lane >> 4;                    // 0/1 -> k0 / k+8 halves
    const int b_r  = wn * 64 + (lane & 7) + ((lane >> 4) << 3);
    const int b_cu = (lane >> 3) & 1;

    float acc[4][8][4];
#pragma unroll
    for (int i = 0; i < 4; i++)
#pragma unroll
        for (int j = 0; j < 8; j++)
#pragma unroll
            for (int e = 0; e < 4; e++) acc[i][j][e] = 0.f;

    const int nchunks = K / BK;      // 64

    fill_stage(sbase, 0, gA, gB, 0, ld_row, ld_unit, K);
    fill_stage(sbase, 1, gA, gB, BK, ld_row, ld_unit, K);

    for (int c = 0; c < nchunks; c++) {
        if (c + 2 < nchunks) {
            fill_stage(sbase, (c + 2) % NSTAGE, gA, gB, (c + 2) * BK, ld_row, ld_unit, K);
            asm volatile("cp.async.wait_group 2;" ::: "memory");
        } else if (c + 1 < nchunks) {
            asm volatile("cp.async.wait_group 1;" ::: "memory");
        } else {
            asm volatile("cp.async.wait_group 0;" ::: "memory");
        }
        __syncthreads();

        const uint32_t st = (uint32_t)(c % NSTAGE) * STAGE_BYTES;
#pragma unroll
        for (int ks = 0; ks < 4; ks++) {
            uint32_t af[4][4];
#pragma unroll
            for (int mt = 0; mt < 4; mt++) {
                uint32_t off = (uint32_t)(a_r + mt * 16) * 128u + (uint32_t)(ks * 2 + a_cu) * 16u;
                LDMATRIX_X4(af[mt][0], af[mt][1], af[mt][2], af[mt][3],
                            sbase + st + SW128(off));
            }
            uint32_t bf[8][2];
#pragma unroll
            for (int ntp = 0; ntp < 4; ntp++) {
                uint32_t off = (uint32_t)(b_r + ntp * 16) * 128u + (uint32_t)(ks * 2 + b_cu) * 16u;
                uint32_t r0, r1, r2, r3;
                LDMATRIX_X4(r0, r1, r2, r3, sbase + st + A_BYTES + SW128(off));
                bf[ntp * 2 + 0][0] = r0; bf[ntp * 2 + 0][1] = r1;
                bf[ntp * 2 + 1][0] = r2; bf[ntp * 2 + 1][1] = r3;
            }
#pragma unroll
            for (int mt = 0; mt < 4; mt++)
#pragma unroll
                for (int nt = 0; nt < 8; nt++)
                    MMA_16816(acc[mt][nt][0], acc[mt][nt][1], acc[mt][nt][2], acc[mt][nt][3],
                              af[mt][0], af[mt][1], af[mt][2], af[mt][3],
                              bf[nt][0], bf[nt][1]);
        }
        __syncthreads();
    }

    // Epilogue: bf16 round + bf16 bias, widen to f32.
    const int gr = lane >> 2;        // 0..7
    const int tg = lane & 3;         // 0..3
#pragma unroll
    for (int nt = 0; nt < 8; nt++) {
        const int col = bn + wn * 64 + nt * 8 + 2 * tg;
        const __nv_bfloat16 bb0 = __float2bfloat16(bias[col]);
        const __nv_bfloat16 bb1 = __float2bfloat16(bias[col + 1]);
#pragma unroll
        for (int mt = 0; mt < 4; mt++) {
            const int row0 = bm + wm * 64 + mt * 16 + gr;
            float2 v0, v1;
            v0.x = __bfloat162float(__hadd(__float2bfloat16(acc[mt][nt][0]), bb0));
            v0.y = __bfloat162float(__hadd(__float2bfloat16(acc[mt][nt][1]), bb1));
            v1.x = __bfloat162float(__hadd(__float2bfloat16(acc[mt][nt][2]), bb0));
            v1.y = __bfloat162float(__hadd(__float2bfloat16(acc[mt][nt][3]), bb1));
            *reinterpret_cast<float2*>(&out[(size_t)row0 * N + col]) = v0;
            *reinterpret_cast<float2*>(&out[(size_t)(row0 + 8) * N + col]) = v1;
        }
    }
}

// ===========================================================================
extern "C" void kernel_launch(void* const* d_in, const int* in_sizes, int n_in,
                              void* d_out, int out_size) {
    const float* x    = (const float*)d_in[0];
    const float* w    = (const float*)d_in[1];
    const float* ws   = (const float*)d_in[2];
    const float* bias = (const float*)d_in[3];
    float* out = (float*)d_out;

    long long nx = in_sizes[0];          // M*K
    long long nw = in_sizes[1];          // N*K
    int N = in_sizes[3];
    int K = (int)(nw / N);
    int M = (int)(nx / K);

    reset_kernel<<<1, 1>>>();
    amax_kernel<<<1024, 256>>>(x, nx >> 2);
    quant_kernel<<<2048, 256>>>(x, nx >> 2);
    prep_w_kernel<<<1024, 256>>>(w, ws, nw >> 2);

    static int smem_set = 0;
    if (!smem_set) {
        cudaFuncSetAttribute(gemm_hmma_kernel,
                             cudaFuncAttributeMaxDynamicSharedMemorySize, NSTAGE * STAGE_BYTES);
        smem_set = 1;
    }
    dim3 grid(N / BN, M / BM);
    gemm_hmma_kernel<<<grid, 256, NSTAGE * STAGE_BYTES>>>(bias, out, M, N, K);
}

// round 6
// speedup vs baseline: 1.0505x; 1.0505x over previous
#include <cuda_runtime.h>
#include <cuda_bf16.h>
#include <cuda_fp8.h>
#include <cstdint>

// ===========================================================================
// Problem-fixed maxima (B=4,S=2048,K=4096,N=4096)
#define M_FIX 8192
#define N_FIX 4096
#define K_FIX 4096

__device__ __nv_bfloat16 g_A[(size_t)M_FIX * K_FIX];   // bf16 dequantized activations
__device__ __nv_bfloat16 g_B[(size_t)N_FIX * K_FIX];   // bf16 scaled weights
__device__ unsigned int  g_amax_bits;

// ===========================================================================
__global__ void reset_kernel() { g_amax_bits = 0u; }

__global__ void amax_kernel(const float* __restrict__ x, long long n4) {
    const float4* x4 = reinterpret_cast<const float4*>(x);
    float m = 0.f;
    long long stride = (long long)gridDim.x * blockDim.x;
    for (long long i = blockIdx.x * (long long)blockDim.x + threadIdx.x; i < n4; i += stride) {
        float4 v = x4[i];
        m = fmaxf(m, fabsf(__bfloat162float(__float2bfloat16(v.x))));
        m = fmaxf(m, fabsf(__bfloat162float(__float2bfloat16(v.y))));
        m = fmaxf(m, fabsf(__bfloat162float(__float2bfloat16(v.z))));
        m = fmaxf(m, fabsf(__bfloat162float(__float2bfloat16(v.w))));
    }
#pragma unroll
    for (int o = 16; o > 0; o >>= 1) m = fmaxf(m, __shfl_xor_sync(0xffffffffu, m, o));
    __shared__ float sm[32];
    int lane = threadIdx.x & 31, w = threadIdx.x >> 5;
    if (lane == 0) sm[w] = m;
    __syncthreads();
    if (w == 0) {
        int nw = (blockDim.x + 31) >> 5;
        m = (lane < nw) ? sm[lane] : 0.f;
#pragma unroll
        for (int o = 16; o > 0; o >>= 1) m = fmaxf(m, __shfl_xor_sync(0xffffffffu, m, o));
        if (lane == 0) atomicMax(&g_amax_bits, __float_as_uint(m));
    }
}

__device__ __forceinline__ unsigned short quant1(float v, float scale, __nv_bfloat16 sb) {
    float xf = __bfloat162float(__float2bfloat16(v));    // bf16(x)
    float q  = __fdiv_rn(xf, scale);
    q = fminf(fmaxf(q, -448.0f), 448.0f);
    __nv_fp8_e4m3 f8(q);
    float fq = (float)f8;
    return __bfloat16_as_ushort(__hmul(__float2bfloat16(fq), sb));
}

__global__ void quant_kernel(const float* __restrict__ x, long long n4) {
    float amax  = __uint_as_float(g_amax_bits);
    float scale = fmaxf(amax, 1e-12f) / 448.0f;
    __nv_bfloat16 sb = __float2bfloat16(scale);
    const float4* x4 = reinterpret_cast<const float4*>(x);
    ushort4* a4 = reinterpret_cast<ushort4*>(g_A);
    long long stride = (long long)gridDim.x * blockDim.x;
    for (long long i = blockIdx.x * (long long)blockDim.x + threadIdx.x; i < n4; i += stride) {
        float4 v = x4[i];
        ushort4 o;
        o.x = quant1(v.x, scale, sb);
        o.y = quant1(v.y, scale, sb);
        o.z = quant1(v.z, scale, sb);
        o.w = quant1(v.w, scale, sb);
        a4[i] = o;
    }
}

__global__ void prep_w_kernel(const float* __restrict__ w,
                              const float* __restrict__ wscale, long long n4) {
    __nv_bfloat16 sb = __float2bfloat16(wscale[0]);
    const float4* w4 = reinterpret_cast<const float4*>(w);
    ushort4* b4 = reinterpret_cast<ushort4*>(g_B);
    long long stride = (long long)gridDim.x * blockDim.x;
    for (long long i = blockIdx.x * (long long)blockDim.x + threadIdx.x; i < n4; i += stride) {
        float4 v = w4[i];
        ushort4 o;
        o.x = __bfloat16_as_ushort(__hmul(__float2bfloat16(v.x), sb));
        o.y = __bfloat16_as_ushort(__hmul(__float2bfloat16(v.y), sb));
        o.z = __bfloat16_as_ushort(__hmul(__float2bfloat16(v.z), sb));
        o.w = __bfloat16_as_ushort(__hmul(__float2bfloat16(v.w), sb));
        b4[i] = o;
    }
}

// ===========================================================================
// HMMA GEMM: 256x128 CTA tile, 512 threads = 16 warps (4M x 4N), warp 64x32.
// BK=64, 3-stage cp.async pipeline (144 KB smem), SW128 swizzle,
// ldmatrix + mma.sync m16n8k16. out_f32 = float( bf16(acc) + bf16(bias) )

#define BM 256
#define BN 128
#define BK 64
#define A_BYTES (BM * 128)               // 32 KB
#define B_BYTES (BN * 128)               // 16 KB
#define STAGE_BYTES (A_BYTES + B_BYTES)  // 48 KB
#define NSTAGE 3
#define SW128(off) ((off) ^ (((off) >> 3) & 0x70))

#define CP_ASYNC_16(dst, src) \
    asm volatile("cp.async.cg.shared.global [%0], [%1], 16;" :: "r"(dst), "l"(src))
#define CP_COMMIT() asm volatile("cp.async.commit_group;" ::: "memory")

#define LDMATRIX_X4(r0, r1, r2, r3, addr) \
    asm volatile("ldmatrix.sync.aligned.m8n8.x4.shared.b16 {%0,%1,%2,%3}, [%4];" \
        : "=r"(r0), "=r"(r1), "=r"(r2), "=r"(r3) : "r"(addr))

#define MMA_16816(c0,c1,c2,c3, a0,a1,a2,a3, b0,b1) \
    asm volatile("mma.sync.aligned.m16n8k16.row.col.f32.bf16.bf16.f32 " \
        "{%0,%1,%2,%3}, {%4,%5,%6,%7}, {%8,%9}, {%0,%1,%2,%3};" \
        : "+f"(c0), "+f"(c1), "+f"(c2), "+f"(c3) \
        : "r"(a0), "r"(a1), "r"(a2), "r"(a3), "r"(b0), "r"(b1))

__device__ __forceinline__ uint32_t smem_u32(const void* p) {
    uint32_t a;
    asm("{ .reg .u64 t; cvta.to.shared.u64 t, %1; cvt.u32.u64 %0, t; }" : "=r"(a) : "l"(p));
    return a;
}

// 512 threads: ld_row = tid>>3 in 0..63, ld_unit = tid&7.
// A: 256 rows = 4 iters of 64;  B: 128 rows = 2 iters of 64.
__device__ __forceinline__ void fill_stage(uint32_t sbase, int stage,
                                           const __nv_bfloat16* gA, const __nv_bfloat16* gB,
                                           int k0, int ld_row, int ld_unit, int K) {
    const uint32_t st = (uint32_t)stage * STAGE_BYTES;
#pragma unroll
    for (int it = 0; it < 4; it++) {
        uint32_t off = (uint32_t)(ld_row + it * 64) * 128u + (uint32_t)ld_unit * 16u;
        CP_ASYNC_16(sbase + st + SW128(off), gA + (size_t)(it * 64) * K + k0);
    }
#pragma unroll
    for (int it = 0; it < 2; it++) {
        uint32_t off = (uint32_t)(ld_row + it * 64) * 128u + (uint32_t)ld_unit * 16u;
        CP_ASYNC_16(sbase + st + A_BYTES + SW128(off), gB + (size_t)(it * 64) * K + k0);
    }
    CP_COMMIT();
}

__global__ __launch_bounds__(512, 1) void gemm_hmma_kernel(const float* __restrict__ bias,
                                                           float* __restrict__ out,
                                                           int M, int N, int K) {
    extern __shared__ char smem[];
    const uint32_t sbase = smem_u32(smem);

    const int tid  = threadIdx.x;
    const int wid  = tid >> 5;
    const int lane = tid & 31;
    const int wm = wid & 3;          // 0..3 -> 64-row slice
    const int wn = wid >> 2;         // 0..3 -> 32-col slice
    const int bm = blockIdx.y * BM;
    const int bn = blockIdx.x * BN;

    const int ld_row  = tid >> 3;    // 0..63
    const int ld_unit = tid & 7;     // 16B unit within 128B row
    const __nv_bfloat16* gA = g_A + (size_t)(bm + ld_row) * K + ld_unit * 8;
    const __nv_bfloat16* gB = g_B + (size_t)(bn + ld_row) * K + ld_unit * 8;

    // ldmatrix addressing (same per-warp pattern as the round-4 winner)
    const int a_r  = wm * 64 + (lane & 15);
    const int a_cu = lane >> 4;                    // 0/1 -> k0 / k+8 halves
    const int b_r  = wn * 32 + (lane & 7) + ((lane >> 4) << 3);
    const int b_cu = (lane >> 3) & 1;

    float acc[4][4][4];
#pragma unroll
    for (int i = 0; i < 4; i++)
#pragma unroll
        for (int j = 0; j < 4; j++)
#pragma unroll
            for (int e = 0; e < 4; e++) acc[i][j][e] = 0.f;

    const int nchunks = K / BK;      // 64

    fill_stage(sbase, 0, gA, gB, 0, ld_row, ld_unit, K);
    fill_stage(sbase, 1, gA, gB, BK, ld_row, ld_unit, K);

    for (int c = 0; c < nchunks; c++) {
        if (c + 2 < nchunks) {
            fill_stage(sbase, (c + 2) % NSTAGE, gA, gB, (c + 2) * BK, ld_row, ld_unit, K);
            asm volatile("cp.async.wait_group 2;" ::: "memory");
        } else if (c + 1 < nchunks) {
            asm volatile("cp.async.wait_group 1;" ::: "memory");
        } else {
            asm volatile("cp.async.wait_group 0;" ::: "memory");
        }
        __syncthreads();

        const uint32_t st = (uint32_t)(c % NSTAGE) * STAGE_BYTES;
#pragma unroll
        for (int ks = 0; ks < 4; ks++) {
            uint32_t af[4][4];
#pragma unroll
            for (int mt = 0; mt < 4; mt++) {
                uint32_t off = (uint32_t)(a_r + mt * 16) * 128u + (uint32_t)(ks * 2 + a_cu) * 16u;
                LDMATRIX_X4(af[mt][0], af[mt][1], af[mt][2], af[mt][3],
                            sbase + st + SW128(off));
            }
            uint32_t bf[4][2];
#pragma unroll
            for (int ntp = 0; ntp < 2; ntp++) {
                uint32_t off = (uint32_t)(b_r + ntp * 16) * 128u + (uint32_t)(ks * 2 + b_cu) * 16u;
                uint32_t r0, r1, r2, r3;
                LDMATRIX_X4(r0, r1, r2, r3, sbase + st + A_BYTES + SW128(off));
                bf[ntp * 2 + 0][0] = r0; bf[ntp * 2 + 0][1] = r1;
                bf[ntp * 2 + 1][0] = r2; bf[ntp * 2 + 1][1] = r3;
            }
#pragma unroll
            for (int mt = 0; mt < 4; mt++)
#pragma unroll
                for (int nt = 0; nt < 4; nt++)
                    MMA_16816(acc[mt][nt][0], acc[mt][nt][1], acc[mt][nt][2], acc[mt][nt][3],
                              af[mt][0], af[mt][1], af[mt][2], af[mt][3],
                              bf[nt][0], bf[nt][1]);
        }
        __syncthreads();
    }

    // Epilogue: bf16 round + bf16 bias, widen to f32.
    const int gr = lane >> 2;        // 0..7
    const int tg = lane & 3;         // 0..3
#pragma unroll
    for (int nt = 0; nt < 4; nt++) {
        const int col = bn + wn * 32 + nt * 8 + 2 * tg;
        const __nv_bfloat16 bb0 = __float2bfloat16(bias[col]);
        const __nv_bfloat16 bb1 = __float2bfloat16(bias[col + 1]);
#pragma unroll
        for (int mt = 0; mt < 4; mt++) {
            const int row0 = bm + wm * 64 + mt * 16 + gr;
            float2 v0, v1;
            v0.x = __bfloat162float(__hadd(__float2bfloat16(acc[mt][nt][0]), bb0));
            v0.y = __bfloat162float(__hadd(__float2bfloat16(acc[mt][nt][1]), bb1));
            v1.x = __bfloat162float(__hadd(__float2bfloat16(acc[mt][nt][2]), bb0));
            v1.y = __bfloat162float(__hadd(__float2bfloat16(acc[mt][nt][3]), bb1));
            *reinterpret_cast<float2*>(&out[(size_t)row0 * N + col]) = v0;
            *reinterpret_cast<float2*>(&out[(size_t)(row0 + 8) * N + col]) = v1;
        }
    }
}

// ===========================================================================
extern "C" void kernel_launch(void* const* d_in, const int* in_sizes, int n_in,
                              void* d_out, int out_size) {
    const float* x    = (const float*)d_in[0];
    const float* w    = (const float*)d_in[1];
    const float* ws   = (const float*)d_in[2];
    const float* bias = (const float*)d_in[3];
    float* out = (float*)d_out;

    long long nx = in_sizes[0];          // M*K
    long long nw = in_sizes[1];          // N*K
    int N = in_sizes[3];
    int K = (int)(nw / N);
    int M = (int)(nx / K);

    reset_kernel<<<1, 1>>>();
    amax_kernel<<<1024, 256>>>(x, nx >> 2);
    quant_kernel<<<2048, 256>>>(x, nx >> 2);
    prep_w_kernel<<<1024, 256>>>(w, ws, nw >> 2);

    static int smem_set = 0;
    if (!smem_set) {
        cudaFuncSetAttribute(gemm_hmma_kernel,
                             cudaFuncAttributeMaxDynamicSharedMemorySize, NSTAGE * STAGE_BYTES);
        smem_set = 1;
    }
    dim3 grid(N / BN, M / BM);
    gemm_hmma_kernel<<<grid, 512, NSTAGE * STAGE_BYTES>>>(bias, out, M, N, K);
}

// round 7
// speedup vs baseline: 1.1471x; 1.0920x over previous
#include <cuda_runtime.h>
#include <cuda_bf16.h>
#include <cuda_fp8.h>
#include <cstdint>

// ===========================================================================
// Problem-fixed maxima (B=4,S=2048,K=4096,N=4096)
#define M_FIX 8192
#define N_FIX 4096
#define K_FIX 4096

__device__ __nv_bfloat16 g_A[(size_t)M_FIX * K_FIX];   // bf16 dequantized activations
__device__ __nv_bfloat16 g_B[(size_t)N_FIX * K_FIX];   // bf16 scaled weights
__device__ unsigned int  g_amax_bits;

// ===========================================================================
__global__ void reset_kernel() { g_amax_bits = 0u; }

__global__ void amax_kernel(const float* __restrict__ x, long long n4) {
    const float4* x4 = reinterpret_cast<const float4*>(x);
    float m = 0.f;
    long long stride = (long long)gridDim.x * blockDim.x;
    for (long long i = blockIdx.x * (long long)blockDim.x + threadIdx.x; i < n4; i += stride) {
        float4 v = x4[i];
        m = fmaxf(m, fabsf(__bfloat162float(__float2bfloat16(v.x))));
        m = fmaxf(m, fabsf(__bfloat162float(__float2bfloat16(v.y))));
        m = fmaxf(m, fabsf(__bfloat162float(__float2bfloat16(v.z))));
        m = fmaxf(m, fabsf(__bfloat162float(__float2bfloat16(v.w))));
    }
#pragma unroll
    for (int o = 16; o > 0; o >>= 1) m = fmaxf(m, __shfl_xor_sync(0xffffffffu, m, o));
    __shared__ float sm[32];
    int lane = threadIdx.x & 31, w = threadIdx.x >> 5;
    if (lane == 0) sm[w] = m;
    __syncthreads();
    if (w == 0) {
        int nw = (blockDim.x + 31) >> 5;
        m = (lane < nw) ? sm[lane] : 0.f;
#pragma unroll
        for (int o = 16; o > 0; o >>= 1) m = fmaxf(m, __shfl_xor_sync(0xffffffffu, m, o));
        if (lane == 0) atomicMax(&g_amax_bits, __float_as_uint(m));
    }
}

__device__ __forceinline__ unsigned short quant1(float v, float scale, __nv_bfloat16 sb) {
    float xf = __bfloat162float(__float2bfloat16(v));    // bf16(x)
    float q  = __fdiv_rn(xf, scale);
    q = fminf(fmaxf(q, -448.0f), 448.0f);
    __nv_fp8_e4m3 f8(q);
    float fq = (float)f8;
    return __bfloat16_as_ushort(__hmul(__float2bfloat16(fq), sb));
}

// Fused: blocks [0, QBLKS) quantize x -> g_A ; blocks [QBLKS, QBLKS+WBLKS) scale w -> g_B
#define QBLKS 2048
#define WBLKS 1024
__global__ void prep_fused_kernel(const float* __restrict__ x, long long nx4,
                                  const float* __restrict__ w,
                                  const float* __restrict__ wscale, long long nw4) {
    if (blockIdx.x < QBLKS) {
        float amax  = __uint_as_float(g_amax_bits);
        float scale = fmaxf(amax, 1e-12f) / 448.0f;
        __nv_bfloat16 sb = __float2bfloat16(scale);
        const float4* x4 = reinterpret_cast<const float4*>(x);
        ushort4* a4 = reinterpret_cast<ushort4*>(g_A);
        long long stride = (long long)QBLKS * blockDim.x;
        for (long long i = blockIdx.x * (long long)blockDim.x + threadIdx.x; i < nx4; i += stride) {
            float4 v = x4[i];
            ushort4 o;
            o.x = quant1(v.x, scale, sb);
            o.y = quant1(v.y, scale, sb);
            o.z = quant1(v.z, scale, sb);
            o.w = quant1(v.w, scale, sb);
            a4[i] = o;
        }
    } else {
        __nv_bfloat16 sb = __float2bfloat16(wscale[0]);
        const float4* w4 = reinterpret_cast<const float4*>(w);
        ushort4* b4 = reinterpret_cast<ushort4*>(g_B);
        long long stride = (long long)WBLKS * blockDim.x;
        for (long long i = (blockIdx.x - QBLKS) * (long long)blockDim.x + threadIdx.x;
             i < nw4; i += stride) {
            float4 v = w4[i];
            ushort4 o;
            o.x = __bfloat16_as_ushort(__hmul(__float2bfloat16(v.x), sb));
            o.y = __bfloat16_as_ushort(__hmul(__float2bfloat16(v.y), sb));
            o.z = __bfloat16_as_ushort(__hmul(__float2bfloat16(v.z), sb));
            o.w = __bfloat16_as_ushort(__hmul(__float2bfloat16(v.w), sb));
            b4[i] = o;
        }
    }
}

// ===========================================================================
// HMMA GEMM: round-4 winning config + 3-stage pipeline.
// 128x128 CTA tile, BK=64, 8 warps (2M x 4N), warp tile 64x32, 2 CTA/SM.
// out_f32 = float( bf16(acc) + bf16(bias) )

#define BM 128
#define BN 128
#define BK 64
#define A_BYTES (BM * 128)               // 16 KB
#define B_BYTES (BN * 128)               // 16 KB
#define STAGE_BYTES (A_BYTES + B_BYTES)  // 32 KB
#define NSTAGE 3                         // 96 KB total, 2 CTA/SM
#define SW128(off) ((off) ^ (((off) >> 3) & 0x70))

#define CP_ASYNC_16(dst, src) \
    asm volatile("cp.async.cg.shared.global [%0], [%1], 16;" :: "r"(dst), "l"(src))
#define CP_COMMIT() asm volatile("cp.async.commit_group;" ::: "memory")

#define LDMATRIX_X4(r0, r1, r2, r3, addr) \
    asm volatile("ldmatrix.sync.aligned.m8n8.x4.shared.b16 {%0,%1,%2,%3}, [%4];" \
        : "=r"(r0), "=r"(r1), "=r"(r2), "=r"(r3) : "r"(addr))

#define MMA_16816(c0,c1,c2,c3, a0,a1,a2,a3, b0,b1) \
    asm volatile("mma.sync.aligned.m16n8k16.row.col.f32.bf16.bf16.f32 " \
        "{%0,%1,%2,%3}, {%4,%5,%6,%7}, {%8,%9}, {%0,%1,%2,%3};" \
        : "+f"(c0), "+f"(c1), "+f"(c2), "+f"(c3) \
        : "r"(a0), "r"(a1), "r"(a2), "r"(a3), "r"(b0), "r"(b1))

__device__ __forceinline__ uint32_t smem_u32(const void* p) {
    uint32_t a;
    asm("{ .reg .u64 t; cvta.to.shared.u64 t, %1; cvt.u32.u64 %0, t; }" : "=r"(a) : "l"(p));
    return a;
}

__device__ __forceinline__ void fill_stage(uint32_t sbase, int stage,
                                           const __nv_bfloat16* gA, const __nv_bfloat16* gB,
                                           int k0, int ld_row, int ld_unit, int K) {
    const uint32_t st = (uint32_t)stage * STAGE_BYTES;
#pragma unroll
    for (int it = 0; it < 4; it++) {
        uint32_t off = (uint32_t)(ld_row + it * 32) * 128u + (uint32_t)ld_unit * 16u;
        uint32_t sw = SW128(off);
        CP_ASYNC_16(sbase + st + sw, gA + (size_t)(it * 32) * K + k0);
        CP_ASYNC_16(sbase + st + A_BYTES + sw, gB + (size_t)(it * 32) * K + k0);
    }
    CP_COMMIT();
}

__global__ __launch_bounds__(256, 2) void gemm_hmma_kernel(const float* __restrict__ bias,
                                                           float* __restrict__ out,
                                                           int M, int N, int K) {
    extern __shared__ char smem[];
    const uint32_t sbase = smem_u32(smem);

    const int tid  = threadIdx.x;
    const int wid  = tid >> 5;
    const int lane = tid & 31;
    const int wm = wid & 1;          // 0..1 -> 64-row slice
    const int wn = wid >> 1;         // 0..3 -> 32-col slice
    const int bm = blockIdx.y * BM;
    const int bn = blockIdx.x * BN;

    const int ld_row  = tid >> 3;    // 0..31
    const int ld_unit = tid & 7;     // 16B unit within 128B row
    const __nv_bfloat16* gA = g_A + (size_t)(bm + ld_row) * K + ld_unit * 8;
    const __nv_bfloat16* gB = g_B + (size_t)(bn + ld_row) * K + ld_unit * 8;

    // ldmatrix addressing
    const int a_r  = wm * 64 + (lane & 15);
    const int a_cu = lane >> 4;                 // 0/1 -> k0 / k+8 halves
    const int b_r  = wn * 32 + (lane & 7) + ((lane >> 4) << 3);
    const int b_cu = (lane >> 3) & 1;

    float acc[4][4][4];
#pragma unroll
    for (int i = 0; i < 4; i++)
#pragma unroll
        for (int j = 0; j < 4; j++)
#pragma unroll
            for (int e = 0; e < 4; e++) acc[i][j][e] = 0.f;

    const int nchunks = K / BK;      // 64

    fill_stage(sbase, 0, gA, gB, 0, ld_row, ld_unit, K);
    fill_stage(sbase, 1, gA, gB, BK, ld_row, ld_unit, K);

    for (int c = 0; c < nchunks; c++) {
        if (c + 2 < nchunks) {
            fill_stage(sbase, (c + 2) % NSTAGE, gA, gB, (c + 2) * BK, ld_row, ld_unit, K);
            asm volatile("cp.async.wait_group 2;" ::: "memory");
        } else if (c + 1 < nchunks) {
            asm volatile("cp.async.wait_group 1;" ::: "memory");
        } else {
            asm volatile("cp.async.wait_group 0;" ::: "memory");
        }
        __syncthreads();

        const uint32_t st = (uint32_t)(c % NSTAGE) * STAGE_BYTES;
#pragma unroll
        for (int ks = 0; ks < 4; ks++) {
            uint32_t af[4][4];
#pragma unroll
            for (int mt = 0; mt < 4; mt++) {
                uint32_t off = (uint32_t)(a_r + mt * 16) * 128u + (uint32_t)(ks * 2 + a_cu) * 16u;
                LDMATRIX_X4(af[mt][0], af[mt][1], af[mt][2], af[mt][3],
                            sbase + st + SW128(off));
            }
            uint32_t bf[4][2];
#pragma unroll
            for (int ntp = 0; ntp < 2; ntp++) {
                uint32_t off = (uint32_t)(b_r + ntp * 16) * 128u + (uint32_t)(ks * 2 + b_cu) * 16u;
                uint32_t r0, r1, r2, r3;
                LDMATRIX_X4(r0, r1, r2, r3, sbase + st + A_BYTES + SW128(off));
                bf[ntp * 2 + 0][0] = r0; bf[ntp * 2 + 0][1] = r1;
                bf[ntp * 2 + 1][0] = r2; bf[ntp * 2 + 1][1] = r3;
            }
#pragma unroll
            for (int mt = 0; mt < 4; mt++)
#pragma unroll
                for (int nt = 0; nt < 4; nt++)
                    MMA_16816(acc[mt][nt][0], acc[mt][nt][1], acc[mt][nt][2], acc[mt][nt][3],
                              af[mt][0], af[mt][1], af[mt][2], af[mt][3],
                              bf[nt][0], bf[nt][1]);
        }
        __syncthreads();
    }

    // Epilogue: bf16 round + bf16 bias (exact reference semantics), widen to f32.
    const int gr = lane >> 2;        // 0..7
    const int tg = lane & 3;         // 0..3
#pragma unroll
    for (int nt = 0; nt < 4; nt++) {
        const int col = bn + wn * 32 + nt * 8 + 2 * tg;
        const __nv_bfloat16 bb0 = __float2bfloat16(bias[col]);
        const __nv_bfloat16 bb1 = __float2bfloat16(bias[col + 1]);
#pragma unroll
        for (int mt = 0; mt < 4; mt++) {
            const int row0 = bm + wm * 64 + mt * 16 + gr;
            float2 v0, v1;
            v0.x = __bfloat162float(__hadd(__float2bfloat16(acc[mt][nt][0]), bb0));
            v0.y = __bfloat162float(__hadd(__float2bfloat16(acc[mt][nt][1]), bb1));
            v1.x = __bfloat162float(__hadd(__float2bfloat16(acc[mt][nt][2]), bb0));
            v1.y = __bfloat162float(__hadd(__float2bfloat16(acc[mt][nt][3]), bb1));
            *reinterpret_cast<float2*>(&out[(size_t)row0 * N + col]) = v0;
            *reinterpret_cast<float2*>(&out[(size_t)(row0 + 8) * N + col]) = v1;
        }
    }
}

// ===========================================================================
extern "C" void kernel_launch(void* const* d_in, const int* in_sizes, int n_in,
                              void* d_out, int out_size) {
    const float* x    = (const float*)d_in[0];
    const float* w    = (const float*)d_in[1];
    const float* ws   = (const float*)d_in[2];
    const float* bias = (const float*)d_in[3];
    float* out = (float*)d_out;

    long long nx = in_sizes[0];          // M*K
    long long nw = in_sizes[1];          // N*K
    int N = in_sizes[3];
    int K = (int)(nw / N);
    int M = (int)(nx / K);

    reset_kernel<<<1, 1>>>();
    amax_kernel<<<1024, 256>>>(x, nx >> 2);
    prep_fused_kernel<<<QBLKS + WBLKS, 256>>>(x, nx >> 2, w, ws, nw >> 2);

    static int smem_set = 0;
    if (!smem_set) {
        cudaFuncSetAttribute(gemm_hmma_kernel,
                             cudaFuncAttributeMaxDynamicSharedMemorySize, NSTAGE * STAGE_BYTES);
        smem_set = 1;
    }
    dim3 grid(N / BN, M / BM);
    gemm_hmma_kernel<<<grid, 256, NSTAGE * STAGE_BYTES>>>(bias, out, M, N, K);
}